// round 6
// baseline (speedup 1.0000x reference)
#include <cuda_runtime.h>
#include <cstdint>

#define D 128
#define NMAX 100000
#define EMAX 800000

// -------- scratch (device globals; no allocations allowed) --------
__device__ float g_h[(size_t)NMAX * D];   // x @ W^T
__device__ float g_deg[NMAX];
__device__ float g_dinv[NMAX];
__device__ int   g_rows[EMAX];
__device__ int   g_cols[EMAX];
__device__ int   g_sr[EMAX];              // row ids sorted by destination col
__device__ int   g_off[NMAX + 1];         // CSR offsets (by col)
__device__ int   g_cursor[NMAX];
__device__ float g_sum[D];
__device__ float g_sumsq[D];
__device__ float g_mean[D];
__device__ float g_scale[D];
__device__ int   g_is64;

// -------- edge dtype detection (int64 vs int32) --------
// Node ids < 2^31. int64 layout => every odd 32-bit word (high half) is 0.
__global__ void detect_kernel(const unsigned int* __restrict__ w) {
    if (threadIdx.x == 0) {
        int is64 = 1;
        for (int i = 1; i < 128; i += 2)
            if (w[i] != 0u) { is64 = 0; break; }
        g_is64 = is64;
    }
}

// -------- zero scratch (precedes convert: deg atomics fused there) --------
__global__ void zero_kernel(int n) {
    int i = blockIdx.x * blockDim.x + threadIdx.x;
    if (i < n) g_deg[i] = 0.f;
    if (i < D) { g_sum[i] = 0.f; g_sumsq[i] = 0.f; }
}

// -------- convert edges to int32 staging + fused degree histogram --------
__global__ void convert_kernel(const void* __restrict__ ei, int E) {
    int e = blockIdx.x * blockDim.x + threadIdx.x;
    if (e >= E) return;
    int r, c;
    if (g_is64) {
        const long long* p = (const long long*)ei;
        r = (int)p[e];
        c = (int)p[(size_t)E + e];
    } else {
        const int* p = (const int*)ei;
        r = p[e];
        c = p[(size_t)E + e];
    }
    g_rows[e] = r;
    g_cols[e] = c;
    atomicAdd(&g_deg[c], 1.0f);   // degree over destination (col)
}

__global__ void dinv_kernel(int n) {
    int i = blockIdx.x * blockDim.x + threadIdx.x;
    if (i < n) {
        float d = g_deg[i];
        g_dinv[i] = (d > 0.f) ? rsqrtf(d) : 0.f;
    }
}

// -------- single-block exclusive prefix scan of degrees -> g_off, g_cursor --
__global__ void scan_kernel(int n, int E) {
    __shared__ int ssum[1024];
    int t = threadIdx.x;
    int chunk = (n + 1023) / 1024;
    int b = t * chunk;
    int e = min(b + chunk, n);
    int s = 0;
    for (int i = b; i < e; i++) s += (int)g_deg[i];
    ssum[t] = s;
    __syncthreads();
    // Hillis-Steele inclusive scan over 1024 partials
    for (int d = 1; d < 1024; d <<= 1) {
        int x = (t >= d) ? ssum[t - d] : 0;
        __syncthreads();
        ssum[t] += x;
        __syncthreads();
    }
    int run = ssum[t] - s;   // exclusive prefix of this thread's chunk
    for (int i = b; i < e; i++) {
        g_off[i] = run;
        g_cursor[i] = run;
        run += (int)g_deg[i];
    }
    if (t == 1023) g_off[n] = E;
}

// -------- bucket edges by destination col --------
__global__ void bucket_kernel(int E) {
    int e = blockIdx.x * blockDim.x + threadIdx.x;
    if (e >= E) return;
    int c = g_cols[e];
    int pos = atomicAdd(&g_cursor[c], 1);
    g_sr[pos] = g_rows[e];
}

// -------- GEMM: h = x @ W^T (fp32 register-blocked, FFMA-floor) ------------
// h[i][j] = sum_k x[i][k]*W[j][k]. 128x128 tile/CTA, 256 thr, 8x8 reg tile.
#define WT_STRIDE 132
#define GEMM_SMEM ((128 * WT_STRIDE + 32 * WT_STRIDE) * 4)
__global__ __launch_bounds__(256, 2)
void gemm_kernel(const float* __restrict__ x, const float* __restrict__ W, int n) {
    extern __shared__ float smem[];
    float* Wt  = smem;                       // [128][132]
    float* xsT = smem + 128 * WT_STRIDE;     // [32][132]
    int t  = threadIdx.x;
    int tx = t & 15;      // cols tx*8 .. tx*8+7
    int ty = t >> 4;      // rows ty*8 .. ty*8+7
    int row0 = blockIdx.x * 128;

    for (int idx = t; idx < D * D; idx += 256) {
        int j = idx >> 7, k = idx & 127;
        Wt[k * WT_STRIDE + j] = W[idx];
    }

    float acc[8][8] = {};

    for (int kc = 0; kc < D; kc += 32) {
        __syncthreads();
        for (int i = t; i < 1024; i += 256) {
            int r  = i >> 3;
            int kq = i & 7;
            int gr = row0 + r;
            float4 v = make_float4(0.f, 0.f, 0.f, 0.f);
            if (gr < n) v = *(const float4*)(x + (size_t)gr * D + kc + kq * 4);
            xsT[(kq * 4 + 0) * WT_STRIDE + r] = v.x;
            xsT[(kq * 4 + 1) * WT_STRIDE + r] = v.y;
            xsT[(kq * 4 + 2) * WT_STRIDE + r] = v.z;
            xsT[(kq * 4 + 3) * WT_STRIDE + r] = v.w;
        }
        __syncthreads();

        #pragma unroll 8
        for (int k = 0; k < 32; k++) {
            float a[8], b[8];
            *(float4*)&a[0] = *(const float4*)&xsT[k * WT_STRIDE + ty * 8];
            *(float4*)&a[4] = *(const float4*)&xsT[k * WT_STRIDE + ty * 8 + 4];
            *(float4*)&b[0] = *(const float4*)&Wt[(kc + k) * WT_STRIDE + tx * 8];
            *(float4*)&b[4] = *(const float4*)&Wt[(kc + k) * WT_STRIDE + tx * 8 + 4];
            #pragma unroll
            for (int i = 0; i < 8; i++)
                #pragma unroll
                for (int j = 0; j < 8; j++)
                    acc[i][j] = fmaf(a[i], b[j], acc[i][j]);
        }
    }

    #pragma unroll
    for (int i = 0; i < 8; i++) {
        int gr = row0 + ty * 8 + i;
        if (gr < n) {
            float4* dst = (float4*)(g_h + (size_t)gr * D + tx * 8);
            dst[0] = *(float4*)&acc[i][0];
            dst[1] = *(float4*)&acc[i][4];
        }
    }
}

// -------- aggregation (gather): out[c] = sum_j norm * h[sr[j]] -------------
// One warp per node; accumulate in registers, single store. No atomics.
__global__ void agg_kernel(float* __restrict__ out, int n) {
    int warp = (blockIdx.x * blockDim.x + threadIdx.x) >> 5;
    int lane = threadIdx.x & 31;
    if (warp >= n) return;
    int c = warp;
    int beg = g_off[c], end = g_off[c + 1];
    float dc = g_dinv[c];
    float4 acc = make_float4(0.f, 0.f, 0.f, 0.f);

    int j = beg;
    for (; j + 1 < end; j += 2) {
        int r0 = g_sr[j], r1 = g_sr[j + 1];
        float n0 = dc * g_dinv[r0];
        float n1 = dc * g_dinv[r1];
        float4 v0 = *(const float4*)(g_h + ((size_t)r0 << 7) + (lane << 2));
        float4 v1 = *(const float4*)(g_h + ((size_t)r1 << 7) + (lane << 2));
        acc.x += v0.x * n0 + v1.x * n1;
        acc.y += v0.y * n0 + v1.y * n1;
        acc.z += v0.z * n0 + v1.z * n1;
        acc.w += v0.w * n0 + v1.w * n1;
    }
    if (j < end) {
        int r0 = g_sr[j];
        float n0 = dc * g_dinv[r0];
        float4 v0 = *(const float4*)(g_h + ((size_t)r0 << 7) + (lane << 2));
        acc.x += v0.x * n0; acc.y += v0.y * n0;
        acc.z += v0.z * n0; acc.w += v0.w * n0;
    }
    *(float4*)(out + ((size_t)c << 7) + (lane << 2)) = acc;
}

// -------- per-column sums for BN --------
__global__ void reduce_kernel(const float* __restrict__ agg, int n) {
    int d = threadIdx.x & 127;
    int rsub = threadIdx.x >> 7;
    float s = 0.f, s2 = 0.f;
    for (int row = blockIdx.x * 4 + rsub; row < n; row += gridDim.x * 4) {
        float v = agg[(size_t)row * D + d];
        s += v; s2 += v * v;
    }
    atomicAdd(&g_sum[d], s);
    atomicAdd(&g_sumsq[d], s2);
}

__global__ void stats_kernel(const float* __restrict__ gamma, int n) {
    int d = threadIdx.x;
    float inv_n = 1.0f / (float)n;
    float mean = g_sum[d] * inv_n;
    float var = g_sumsq[d] * inv_n - mean * mean;
    g_mean[d] = mean;                       // linear bias cancels via mean subtraction
    g_scale[d] = rsqrtf(var + 1e-5f) * gamma[d];
}

// -------- epilogue: out = relu((agg-mean)*scale + beta) + x --------
__global__ void final_kernel(float* __restrict__ out, const float* __restrict__ x,
                             const float* __restrict__ beta, int n) {
    int idx = blockIdx.x * blockDim.x + threadIdx.x;
    if (idx >= n * 32) return;
    int d4 = (idx & 31) << 2;
    float4 a = reinterpret_cast<float4*>(out)[idx];
    float4 xv = reinterpret_cast<const float4*>(x)[idx];
    a.x = fmaxf((a.x - g_mean[d4 + 0]) * g_scale[d4 + 0] + beta[d4 + 0], 0.f) + xv.x;
    a.y = fmaxf((a.y - g_mean[d4 + 1]) * g_scale[d4 + 1] + beta[d4 + 1], 0.f) + xv.y;
    a.z = fmaxf((a.z - g_mean[d4 + 2]) * g_scale[d4 + 2] + beta[d4 + 2], 0.f) + xv.z;
    a.w = fmaxf((a.w - g_mean[d4 + 3]) * g_scale[d4 + 3] + beta[d4 + 3], 0.f) + xv.w;
    reinterpret_cast<float4*>(out)[idx] = a;
}

extern "C" void kernel_launch(void* const* d_in, const int* in_sizes, int n_in,
                              void* d_out, int out_size) {
    const float* x     = (const float*)d_in[0];
    const void*  ei    = d_in[1];
    const float* W     = (const float*)d_in[2];
    const float* gamma = (const float*)d_in[4];
    const float* beta  = (const float*)d_in[5];
    int n = in_sizes[0] / D;
    int E = in_sizes[1] / 2;
    float* out = (float*)d_out;

    // zero only the tail beyond N*D (tuple scalar slot); agg writes the rest
    size_t nd = (size_t)n * D;
    if ((size_t)out_size > nd)
        cudaMemsetAsync(out + nd, 0, ((size_t)out_size - nd) * sizeof(float), 0);

    zero_kernel<<<(n + 255) / 256, 256>>>(n);
    detect_kernel<<<1, 32>>>((const unsigned int*)ei);
    convert_kernel<<<(E + 255) / 256, 256>>>(ei, E);   // fused degree
    dinv_kernel<<<(n + 255) / 256, 256>>>(n);
    scan_kernel<<<1, 1024>>>(n, E);
    bucket_kernel<<<(E + 255) / 256, 256>>>(E);

    cudaFuncSetAttribute(gemm_kernel, cudaFuncAttributeMaxDynamicSharedMemorySize, GEMM_SMEM);
    gemm_kernel<<<(n + 127) / 128, 256, GEMM_SMEM>>>(x, W, n);

    agg_kernel<<<((size_t)n * 32 + 255) / 256, 256>>>(out, n);
    reduce_kernel<<<512, 512>>>(out, n);
    stats_kernel<<<1, 128>>>(gamma, n);
    final_kernel<<<(n * 32 + 255) / 256, 256>>>(out, x, beta, n);
}

// round 7
// speedup vs baseline: 1.6029x; 1.6029x over previous
#include <cuda_runtime.h>
#include <cstdint>

#define D 128
#define NMAX 100000
#define EMAX 800000
#define NBMAX 128   // ceil(NMAX/1024)

// -------- scratch (device globals; no allocations allowed) --------
__device__ float g_h[(size_t)NMAX * D];   // x @ W^T
__device__ float g_deg[NMAX];
__device__ float g_dinv[NMAX];
__device__ int   g_rows[EMAX];
__device__ int   g_cols[EMAX];
__device__ int   g_sr[EMAX];              // row ids sorted by destination col
__device__ int   g_off[NMAX + 1];         // CSR offsets (by col)
__device__ int   g_cursor[NMAX];
__device__ int   g_bsum[NBMAX];           // per-block degree sums
__device__ int   g_bpre[NBMAX];           // exclusive prefix of block sums
__device__ float g_sum[D];
__device__ float g_sumsq[D];
__device__ float g_mean[D];
__device__ float g_scale[D];
__device__ int   g_is64;

// -------- edge dtype detection (int64 vs int32) --------
// Node ids < 2^31. int64 layout => every odd 32-bit word (high half) is 0.
__global__ void detect_kernel(const unsigned int* __restrict__ w) {
    if (threadIdx.x == 0) {
        int is64 = 1;
        for (int i = 1; i < 128; i += 2)
            if (w[i] != 0u) { is64 = 0; break; }
        g_is64 = is64;
    }
}

// -------- zero scratch (precedes convert: deg atomics fused there) --------
__global__ void zero_kernel(int n) {
    int i = blockIdx.x * blockDim.x + threadIdx.x;
    if (i < n) g_deg[i] = 0.f;
    if (i < D) { g_sum[i] = 0.f; g_sumsq[i] = 0.f; }
}

// -------- convert edges to int32 staging + fused degree histogram --------
__global__ void convert_kernel(const void* __restrict__ ei, int E) {
    int e = blockIdx.x * blockDim.x + threadIdx.x;
    if (e >= E) return;
    int r, c;
    if (g_is64) {
        const long long* p = (const long long*)ei;
        r = (int)p[e];
        c = (int)p[(size_t)E + e];
    } else {
        const int* p = (const int*)ei;
        r = p[e];
        c = p[(size_t)E + e];
    }
    g_rows[e] = r;
    g_cols[e] = c;
    atomicAdd(&g_deg[c], 1.0f);   // degree over destination (col)
}

// ======== coalesced 3-phase exclusive scan of degrees ========
// Phase A: per-block (1024 elems) scan; within-block exclusive prefix to
// g_off, block total to g_bsum. Thread t handles contiguous [t*4, t*4+4)
// via one 16B load -> fully coalesced across the warp.
__global__ void scanA_kernel(int n) {
    __shared__ int wsum[8];
    int t = threadIdx.x;
    int lane = t & 31, w = t >> 5;
    int base = blockIdx.x * 1024 + t * 4;

    int v0 = 0, v1 = 0, v2 = 0, v3 = 0;
    if (base + 3 < n) {
        float4 f = *(const float4*)(g_deg + base);
        v0 = (int)f.x; v1 = (int)f.y; v2 = (int)f.z; v3 = (int)f.w;
    } else {
        if (base + 0 < n) v0 = (int)g_deg[base + 0];
        if (base + 1 < n) v1 = (int)g_deg[base + 1];
        if (base + 2 < n) v2 = (int)g_deg[base + 2];
        if (base + 3 < n) v3 = (int)g_deg[base + 3];
    }
    int ts = v0 + v1 + v2 + v3;

    int incl = ts;
    #pragma unroll
    for (int d = 1; d < 32; d <<= 1) {
        int u = __shfl_up_sync(0xFFFFFFFFu, incl, d);
        if (lane >= d) incl += u;
    }
    if (lane == 31) wsum[w] = incl;
    __syncthreads();
    if (t == 0) {
        int run = 0;
        #pragma unroll
        for (int i = 0; i < 8; i++) { int x = wsum[i]; wsum[i] = run; run += x; }
    }
    __syncthreads();

    int ex = wsum[w] + incl - ts;   // exclusive prefix within block
    if (base + 3 < n) {
        *(int4*)(g_off + base) = make_int4(ex, ex + v0, ex + v0 + v1, ex + v0 + v1 + v2);
    } else {
        if (base + 0 < n) g_off[base + 0] = ex;
        if (base + 1 < n) g_off[base + 1] = ex + v0;
        if (base + 2 < n) g_off[base + 2] = ex + v0 + v1;
        if (base + 3 < n) g_off[base + 3] = ex + v0 + v1 + v2;
    }
    if (t == 255) g_bsum[blockIdx.x] = wsum[7] + incl;  // block total
}

// Phase B: serial scan of <=128 block sums (one thread; negligible)
__global__ void scanB_kernel(int nb) {
    if (threadIdx.x == 0) {
        int run = 0;
        for (int i = 0; i < nb; i++) { int x = g_bsum[i]; g_bpre[i] = run; run += x; }
    }
}

// Phase C: add block prefixes, init cursor, fused dinv. All coalesced.
__global__ void scanC_kernel(int n, int E) {
    int i = blockIdx.x * blockDim.x + threadIdx.x;
    if (i < n) {
        int off = g_off[i] + g_bpre[i >> 10];
        g_off[i] = off;
        g_cursor[i] = off;
        float d = g_deg[i];
        g_dinv[i] = (d > 0.f) ? rsqrtf(d) : 0.f;
    }
    if (i == 0) g_off[n] = E;
}

// -------- bucket edges by destination col --------
__global__ void bucket_kernel(int E) {
    int e = blockIdx.x * blockDim.x + threadIdx.x;
    if (e >= E) return;
    int c = g_cols[e];
    int pos = atomicAdd(&g_cursor[c], 1);
    g_sr[pos] = g_rows[e];
}

// -------- GEMM: h = x @ W^T (fp32 register-blocked, FFMA-floor) ------------
#define WT_STRIDE 132
#define GEMM_SMEM ((128 * WT_STRIDE + 32 * WT_STRIDE) * 4)
__global__ __launch_bounds__(256, 2)
void gemm_kernel(const float* __restrict__ x, const float* __restrict__ W, int n) {
    extern __shared__ float smem[];
    float* Wt  = smem;                       // [128][132]
    float* xsT = smem + 128 * WT_STRIDE;     // [32][132]
    int t  = threadIdx.x;
    int tx = t & 15;
    int ty = t >> 4;
    int row0 = blockIdx.x * 128;

    for (int idx = t; idx < D * D; idx += 256) {
        int j = idx >> 7, k = idx & 127;
        Wt[k * WT_STRIDE + j] = W[idx];
    }

    float acc[8][8] = {};

    for (int kc = 0; kc < D; kc += 32) {
        __syncthreads();
        for (int i = t; i < 1024; i += 256) {
            int r  = i >> 3;
            int kq = i & 7;
            int gr = row0 + r;
            float4 v = make_float4(0.f, 0.f, 0.f, 0.f);
            if (gr < n) v = *(const float4*)(x + (size_t)gr * D + kc + kq * 4);
            xsT[(kq * 4 + 0) * WT_STRIDE + r] = v.x;
            xsT[(kq * 4 + 1) * WT_STRIDE + r] = v.y;
            xsT[(kq * 4 + 2) * WT_STRIDE + r] = v.z;
            xsT[(kq * 4 + 3) * WT_STRIDE + r] = v.w;
        }
        __syncthreads();

        #pragma unroll 8
        for (int k = 0; k < 32; k++) {
            float a[8], b[8];
            *(float4*)&a[0] = *(const float4*)&xsT[k * WT_STRIDE + ty * 8];
            *(float4*)&a[4] = *(const float4*)&xsT[k * WT_STRIDE + ty * 8 + 4];
            *(float4*)&b[0] = *(const float4*)&Wt[(kc + k) * WT_STRIDE + tx * 8];
            *(float4*)&b[4] = *(const float4*)&Wt[(kc + k) * WT_STRIDE + tx * 8 + 4];
            #pragma unroll
            for (int i = 0; i < 8; i++)
                #pragma unroll
                for (int j = 0; j < 8; j++)
                    acc[i][j] = fmaf(a[i], b[j], acc[i][j]);
        }
    }

    #pragma unroll
    for (int i = 0; i < 8; i++) {
        int gr = row0 + ty * 8 + i;
        if (gr < n) {
            float4* dst = (float4*)(g_h + (size_t)gr * D + tx * 8);
            dst[0] = *(float4*)&acc[i][0];
            dst[1] = *(float4*)&acc[i][4];
        }
    }
}

// -------- aggregation (gather): out[c] = sum_j norm * h[sr[j]] -------------
// One warp per node; register accumulate, single store, no atomics.
__global__ void agg_kernel(float* __restrict__ out, int n) {
    int warp = (blockIdx.x * blockDim.x + threadIdx.x) >> 5;
    int lane = threadIdx.x & 31;
    if (warp >= n) return;
    int c = warp;
    int beg = g_off[c], end = g_off[c + 1];
    float dc = g_dinv[c];
    float4 acc = make_float4(0.f, 0.f, 0.f, 0.f);

    int j = beg;
    for (; j + 1 < end; j += 2) {
        int r0 = g_sr[j], r1 = g_sr[j + 1];
        float n0 = dc * g_dinv[r0];
        float n1 = dc * g_dinv[r1];
        float4 v0 = *(const float4*)(g_h + ((size_t)r0 << 7) + (lane << 2));
        float4 v1 = *(const float4*)(g_h + ((size_t)r1 << 7) + (lane << 2));
        acc.x += v0.x * n0 + v1.x * n1;
        acc.y += v0.y * n0 + v1.y * n1;
        acc.z += v0.z * n0 + v1.z * n1;
        acc.w += v0.w * n0 + v1.w * n1;
    }
    if (j < end) {
        int r0 = g_sr[j];
        float n0 = dc * g_dinv[r0];
        float4 v0 = *(const float4*)(g_h + ((size_t)r0 << 7) + (lane << 2));
        acc.x += v0.x * n0; acc.y += v0.y * n0;
        acc.z += v0.z * n0; acc.w += v0.w * n0;
    }
    *(float4*)(out + ((size_t)c << 7) + (lane << 2)) = acc;
}

// -------- per-column sums for BN --------
__global__ void reduce_kernel(const float* __restrict__ agg, int n) {
    int d = threadIdx.x & 127;
    int rsub = threadIdx.x >> 7;
    float s = 0.f, s2 = 0.f;
    for (int row = blockIdx.x * 4 + rsub; row < n; row += gridDim.x * 4) {
        float v = agg[(size_t)row * D + d];
        s += v; s2 += v * v;
    }
    atomicAdd(&g_sum[d], s);
    atomicAdd(&g_sumsq[d], s2);
}

__global__ void stats_kernel(const float* __restrict__ gamma, int n) {
    int d = threadIdx.x;
    float inv_n = 1.0f / (float)n;
    float mean = g_sum[d] * inv_n;
    float var = g_sumsq[d] * inv_n - mean * mean;
    g_mean[d] = mean;                       // linear bias cancels via mean subtraction
    g_scale[d] = rsqrtf(var + 1e-5f) * gamma[d];
}

// -------- epilogue: out = relu((agg-mean)*scale + beta) + x --------
__global__ void final_kernel(float* __restrict__ out, const float* __restrict__ x,
                             const float* __restrict__ beta, int n) {
    int idx = blockIdx.x * blockDim.x + threadIdx.x;
    if (idx >= n * 32) return;
    int d4 = (idx & 31) << 2;
    float4 a = reinterpret_cast<float4*>(out)[idx];
    float4 xv = reinterpret_cast<const float4*>(x)[idx];
    a.x = fmaxf((a.x - g_mean[d4 + 0]) * g_scale[d4 + 0] + beta[d4 + 0], 0.f) + xv.x;
    a.y = fmaxf((a.y - g_mean[d4 + 1]) * g_scale[d4 + 1] + beta[d4 + 1], 0.f) + xv.y;
    a.z = fmaxf((a.z - g_mean[d4 + 2]) * g_scale[d4 + 2] + beta[d4 + 2], 0.f) + xv.z;
    a.w = fmaxf((a.w - g_mean[d4 + 3]) * g_scale[d4 + 3] + beta[d4 + 3], 0.f) + xv.w;
    reinterpret_cast<float4*>(out)[idx] = a;
}

extern "C" void kernel_launch(void* const* d_in, const int* in_sizes, int n_in,
                              void* d_out, int out_size) {
    const float* x     = (const float*)d_in[0];
    const void*  ei    = d_in[1];
    const float* W     = (const float*)d_in[2];
    const float* gamma = (const float*)d_in[4];
    const float* beta  = (const float*)d_in[5];
    int n = in_sizes[0] / D;
    int E = in_sizes[1] / 2;
    float* out = (float*)d_out;

    // zero only the tail beyond N*D (tuple scalar slot); agg writes the rest
    size_t nd = (size_t)n * D;
    if ((size_t)out_size > nd)
        cudaMemsetAsync(out + nd, 0, ((size_t)out_size - nd) * sizeof(float), 0);

    zero_kernel<<<(n + 255) / 256, 256>>>(n);
    detect_kernel<<<1, 32>>>((const unsigned int*)ei);
    convert_kernel<<<(E + 255) / 256, 256>>>(ei, E);   // fused degree

    int nb = (n + 1023) / 1024;
    scanA_kernel<<<nb, 256>>>(n);
    scanB_kernel<<<1, 32>>>(nb);
    scanC_kernel<<<(n + 255) / 256, 256>>>(n, E);      // fused dinv
    bucket_kernel<<<(E + 255) / 256, 256>>>(E);

    cudaFuncSetAttribute(gemm_kernel, cudaFuncAttributeMaxDynamicSharedMemorySize, GEMM_SMEM);
    gemm_kernel<<<(n + 127) / 128, 256, GEMM_SMEM>>>(x, W, n);

    agg_kernel<<<((size_t)n * 32 + 255) / 256, 256>>>(out, n);
    reduce_kernel<<<512, 512>>>(out, n);
    stats_kernel<<<1, 128>>>(gamma, n);
    final_kernel<<<(n * 32 + 255) / 256, 256>>>(out, x, beta, n);
}

// round 8
// speedup vs baseline: 2.1643x; 1.3502x over previous
#include <cuda_runtime.h>
#include <cuda_bf16.h>
#include <cstdint>

#define D 128
#define NMAX 100000
#define EMAX 800000
#define NBMAX 128   // ceil(NMAX/1024)
#define WPAD 136    // padded bf16 row stride (272B): conflict-free fragments

// -------- scratch (device globals; no allocations allowed) --------
__device__ float g_h[(size_t)NMAX * D];   // x @ W^T
__device__ float g_deg[NMAX];
__device__ float g_dinv[NMAX];
__device__ int   g_rows[EMAX];
__device__ int   g_cols[EMAX];
__device__ int   g_sr[EMAX];              // row ids sorted by destination col
__device__ int   g_off[NMAX + 1];         // CSR offsets (by col)
__device__ int   g_cursor[NMAX];
__device__ int   g_bsum[NBMAX];
__device__ int   g_bpre[NBMAX];
__device__ float g_sum[D];
__device__ float g_sumsq[D];
__device__ float g_mean[D];
__device__ float g_scale[D];
__device__ int   g_is64;
__device__ __align__(16) __nv_bfloat16 g_whi[128 * WPAD];  // W hi, padded
__device__ __align__(16) __nv_bfloat16 g_wlo[128 * WPAD];  // W lo, padded

// -------- edge dtype detection (int64 vs int32) --------
__global__ void detect_kernel(const unsigned int* __restrict__ w) {
    if (threadIdx.x == 0) {
        int is64 = 1;
        for (int i = 1; i < 128; i += 2)
            if (w[i] != 0u) { is64 = 0; break; }
        g_is64 = is64;
    }
}

// -------- zero scratch (precedes convert: deg atomics fused there) --------
__global__ void zero_kernel(int n) {
    int i = blockIdx.x * blockDim.x + threadIdx.x;
    if (i < n) g_deg[i] = 0.f;
    if (i < D) { g_sum[i] = 0.f; g_sumsq[i] = 0.f; }
}

// -------- convert edges to int32 staging + fused degree histogram --------
__global__ void convert_kernel(const void* __restrict__ ei, int E) {
    int e = blockIdx.x * blockDim.x + threadIdx.x;
    if (e >= E) return;
    int r, c;
    if (g_is64) {
        const long long* p = (const long long*)ei;
        r = (int)p[e];
        c = (int)p[(size_t)E + e];
    } else {
        const int* p = (const int*)ei;
        r = p[e];
        c = p[(size_t)E + e];
    }
    g_rows[e] = r;
    g_cols[e] = c;
    atomicAdd(&g_deg[c], 1.0f);
}

// ======== coalesced 3-phase exclusive scan of degrees ========
__global__ void scanA_kernel(int n) {
    __shared__ int wsum[8];
    int t = threadIdx.x;
    int lane = t & 31, w = t >> 5;
    int base = blockIdx.x * 1024 + t * 4;

    int v0 = 0, v1 = 0, v2 = 0, v3 = 0;
    if (base + 3 < n) {
        float4 f = *(const float4*)(g_deg + base);
        v0 = (int)f.x; v1 = (int)f.y; v2 = (int)f.z; v3 = (int)f.w;
    } else {
        if (base + 0 < n) v0 = (int)g_deg[base + 0];
        if (base + 1 < n) v1 = (int)g_deg[base + 1];
        if (base + 2 < n) v2 = (int)g_deg[base + 2];
        if (base + 3 < n) v3 = (int)g_deg[base + 3];
    }
    int ts = v0 + v1 + v2 + v3;

    int incl = ts;
    #pragma unroll
    for (int d = 1; d < 32; d <<= 1) {
        int u = __shfl_up_sync(0xFFFFFFFFu, incl, d);
        if (lane >= d) incl += u;
    }
    if (lane == 31) wsum[w] = incl;
    __syncthreads();
    if (t == 0) {
        int run = 0;
        #pragma unroll
        for (int i = 0; i < 8; i++) { int x = wsum[i]; wsum[i] = run; run += x; }
    }
    __syncthreads();

    int ex = wsum[w] + incl - ts;
    if (base + 3 < n) {
        *(int4*)(g_off + base) = make_int4(ex, ex + v0, ex + v0 + v1, ex + v0 + v1 + v2);
    } else {
        if (base + 0 < n) g_off[base + 0] = ex;
        if (base + 1 < n) g_off[base + 1] = ex + v0;
        if (base + 2 < n) g_off[base + 2] = ex + v0 + v1;
        if (base + 3 < n) g_off[base + 3] = ex + v0 + v1 + v2;
    }
    if (t == 255) g_bsum[blockIdx.x] = wsum[7] + incl;
}

__global__ void scanB_kernel(int nb) {
    if (threadIdx.x == 0) {
        int run = 0;
        for (int i = 0; i < nb; i++) { int x = g_bsum[i]; g_bpre[i] = run; run += x; }
    }
}

__global__ void scanC_kernel(int n, int E) {
    int i = blockIdx.x * blockDim.x + threadIdx.x;
    if (i < n) {
        int off = g_off[i] + g_bpre[i >> 10];
        g_off[i] = off;
        g_cursor[i] = off;
        float d = g_deg[i];
        g_dinv[i] = (d > 0.f) ? rsqrtf(d) : 0.f;
    }
    if (i == 0) g_off[n] = E;
}

// -------- bucket edges by destination col --------
__global__ void bucket_kernel(int E) {
    int e = blockIdx.x * blockDim.x + threadIdx.x;
    if (e >= E) return;
    int c = g_cols[e];
    int pos = atomicAdd(&g_cursor[c], 1);
    g_sr[pos] = g_rows[e];
}

// ======== GEMM via mma.sync bf16 (3-term hi/lo split, fp32 accum) =========
// h[i][j] = sum_k x[i,k]*W[j,k]. A = x row-major, B = W row-major [n][k]
// which is exactly col-major [k][n] for mma ".row.col". 128x128 tile/CTA,
// 8 warps in 2(m)x4(n) grid: each warp 64m x 32n = 4x4 m16n8k16 tiles.
__global__ void prep_w_kernel(const float* __restrict__ W) {
    int i = blockIdx.x * blockDim.x + threadIdx.x;
    if (i >= 128 * 128) return;
    int r = i >> 7, k = i & 127;
    float v = W[i];
    __nv_bfloat16 h = __float2bfloat16(v);
    g_whi[r * WPAD + k] = h;
    g_wlo[r * WPAD + k] = __float2bfloat16(v - __bfloat162float(h));
}

__device__ __forceinline__ void mma16816(float* c, const uint32_t* a,
                                         uint32_t b0, uint32_t b1) {
    asm volatile(
        "mma.sync.aligned.m16n8k16.row.col.f32.bf16.bf16.f32 "
        "{%0,%1,%2,%3}, {%4,%5,%6,%7}, {%8,%9}, {%0,%1,%2,%3};"
        : "+f"(c[0]), "+f"(c[1]), "+f"(c[2]), "+f"(c[3])
        : "r"(a[0]), "r"(a[1]), "r"(a[2]), "r"(a[3]), "r"(b0), "r"(b1));
}

#define SM_WHI 0
#define SM_WLO (128 * WPAD)
#define SM_XHI (2 * 128 * WPAD)
#define SM_XLO (3 * 128 * WPAD)
#define GEMM_SMEM (4 * 128 * WPAD * 2)   // 139264 bytes

__global__ __launch_bounds__(256, 1)
void gemm_mma_kernel(const float* __restrict__ x, int n) {
    extern __shared__ __nv_bfloat16 smem[];
    int t = threadIdx.x;
    int row0 = blockIdx.x * 128;

    // copy precomputed W hi/lo (padded, contiguous) into smem: 2*2176 uint4
    {
        const uint4* srcH = (const uint4*)g_whi;
        const uint4* srcL = (const uint4*)g_wlo;
        uint4* dstH = (uint4*)(smem + SM_WHI);
        uint4* dstL = (uint4*)(smem + SM_WLO);
        #pragma unroll
        for (int i = t; i < 2176; i += 256) { dstH[i] = srcH[i]; dstL[i] = srcL[i]; }
    }
    // load x tile, split into bf16 hi/lo
    #pragma unroll
    for (int i = t; i < 4096; i += 256) {
        int r = i >> 5, c4 = (i & 31) << 2;
        int gr = row0 + r;
        float4 v = make_float4(0.f, 0.f, 0.f, 0.f);
        if (gr < n) v = *(const float4*)(x + (size_t)gr * D + c4);
        __nv_bfloat16 h0 = __float2bfloat16(v.x), h1 = __float2bfloat16(v.y);
        __nv_bfloat16 h2 = __float2bfloat16(v.z), h3 = __float2bfloat16(v.w);
        __nv_bfloat162* ph = (__nv_bfloat162*)(smem + SM_XHI + r * WPAD + c4);
        __nv_bfloat162* pl = (__nv_bfloat162*)(smem + SM_XLO + r * WPAD + c4);
        ph[0] = __nv_bfloat162(h0, h1);
        ph[1] = __nv_bfloat162(h2, h3);
        pl[0] = __nv_bfloat162(__float2bfloat16(v.x - __bfloat162float(h0)),
                               __float2bfloat16(v.y - __bfloat162float(h1)));
        pl[1] = __nv_bfloat162(__float2bfloat16(v.z - __bfloat162float(h2)),
                               __float2bfloat16(v.w - __bfloat162float(h3)));
    }
    __syncthreads();

    int lane = t & 31, wid = t >> 5;
    int wm = wid & 1;          // 2 warps in m: rows wm*64
    int wn = wid >> 1;         // 4 warps in n: cols wn*32
    int rq = lane >> 2;        // 0..7
    int kq = (lane & 3) << 1;  // 0,2,4,6

    float acc[4][4][4] = {};

    #pragma unroll
    for (int ks = 0; ks < 8; ks++) {
        int kb = ks * 16 + kq;
        uint32_t aH[4][4], aL[4][4];
        #pragma unroll
        for (int mi = 0; mi < 4; mi++) {
            int rb = wm * 64 + mi * 16 + rq;
            const __nv_bfloat16* pH = smem + SM_XHI + rb * WPAD + kb;
            const __nv_bfloat16* pL = smem + SM_XLO + rb * WPAD + kb;
            aH[mi][0] = *(const uint32_t*)pH;
            aH[mi][1] = *(const uint32_t*)(pH + 8 * WPAD);
            aH[mi][2] = *(const uint32_t*)(pH + 8);
            aH[mi][3] = *(const uint32_t*)(pH + 8 * WPAD + 8);
            aL[mi][0] = *(const uint32_t*)pL;
            aL[mi][1] = *(const uint32_t*)(pL + 8 * WPAD);
            aL[mi][2] = *(const uint32_t*)(pL + 8);
            aL[mi][3] = *(const uint32_t*)(pL + 8 * WPAD + 8);
        }
        #pragma unroll
        for (int ni = 0; ni < 4; ni++) {
            int nb = wn * 32 + ni * 8 + rq;
            const __nv_bfloat16* pH = smem + SM_WHI + nb * WPAD + kb;
            const __nv_bfloat16* pL = smem + SM_WLO + nb * WPAD + kb;
            uint32_t bH0 = *(const uint32_t*)pH;
            uint32_t bH1 = *(const uint32_t*)(pH + 8);
            uint32_t bL0 = *(const uint32_t*)pL;
            uint32_t bL1 = *(const uint32_t*)(pL + 8);
            #pragma unroll
            for (int mi = 0; mi < 4; mi++) {
                mma16816(acc[mi][ni], aH[mi], bH0, bH1);
                mma16816(acc[mi][ni], aH[mi], bL0, bL1);
                mma16816(acc[mi][ni], aL[mi], bH0, bH1);
            }
        }
    }

    // epilogue: c0,c1 -> (row, col..col+1); c2,c3 -> (row+8, ...)
    #pragma unroll
    for (int mi = 0; mi < 4; mi++) {
        int r0 = row0 + wm * 64 + mi * 16 + rq;
        #pragma unroll
        for (int ni = 0; ni < 4; ni++) {
            int cc = wn * 32 + ni * 8 + kq;
            if (r0 < n)
                *(float2*)(g_h + (size_t)r0 * D + cc)
                    = make_float2(acc[mi][ni][0], acc[mi][ni][1]);
            if (r0 + 8 < n)
                *(float2*)(g_h + (size_t)(r0 + 8) * D + cc)
                    = make_float2(acc[mi][ni][2], acc[mi][ni][3]);
        }
    }
}

// -------- aggregation (gather): out[c] = sum_j norm * h[sr[j]] -------------
__global__ void agg_kernel(float* __restrict__ out, int n) {
    int warp = (blockIdx.x * blockDim.x + threadIdx.x) >> 5;
    int lane = threadIdx.x & 31;
    if (warp >= n) return;
    int c = warp;
    int beg = g_off[c], end = g_off[c + 1];
    float dc = g_dinv[c];
    float4 acc = make_float4(0.f, 0.f, 0.f, 0.f);

    int j = beg;
    for (; j + 1 < end; j += 2) {
        int r0 = g_sr[j], r1 = g_sr[j + 1];
        float n0 = dc * g_dinv[r0];
        float n1 = dc * g_dinv[r1];
        float4 v0 = *(const float4*)(g_h + ((size_t)r0 << 7) + (lane << 2));
        float4 v1 = *(const float4*)(g_h + ((size_t)r1 << 7) + (lane << 2));
        acc.x += v0.x * n0 + v1.x * n1;
        acc.y += v0.y * n0 + v1.y * n1;
        acc.z += v0.z * n0 + v1.z * n1;
        acc.w += v0.w * n0 + v1.w * n1;
    }
    if (j < end) {
        int r0 = g_sr[j];
        float n0 = dc * g_dinv[r0];
        float4 v0 = *(const float4*)(g_h + ((size_t)r0 << 7) + (lane << 2));
        acc.x += v0.x * n0; acc.y += v0.y * n0;
        acc.z += v0.z * n0; acc.w += v0.w * n0;
    }
    *(float4*)(out + ((size_t)c << 7) + (lane << 2)) = acc;
}

// -------- per-column sums for BN --------
__global__ void reduce_kernel(const float* __restrict__ agg, int n) {
    int d = threadIdx.x & 127;
    int rsub = threadIdx.x >> 7;
    float s = 0.f, s2 = 0.f;
    for (int row = blockIdx.x * 4 + rsub; row < n; row += gridDim.x * 4) {
        float v = agg[(size_t)row * D + d];
        s += v; s2 += v * v;
    }
    atomicAdd(&g_sum[d], s);
    atomicAdd(&g_sumsq[d], s2);
}

__global__ void stats_kernel(const float* __restrict__ gamma, int n) {
    int d = threadIdx.x;
    float inv_n = 1.0f / (float)n;
    float mean = g_sum[d] * inv_n;
    float var = g_sumsq[d] * inv_n - mean * mean;
    g_mean[d] = mean;                       // linear bias cancels via mean subtraction
    g_scale[d] = rsqrtf(var + 1e-5f) * gamma[d];
}

// -------- epilogue: out = relu((agg-mean)*scale + beta) + x --------
__global__ void final_kernel(float* __restrict__ out, const float* __restrict__ x,
                             const float* __restrict__ beta, int n) {
    int idx = blockIdx.x * blockDim.x + threadIdx.x;
    if (idx >= n * 32) return;
    int d4 = (idx & 31) << 2;
    float4 a = reinterpret_cast<float4*>(out)[idx];
    float4 xv = reinterpret_cast<const float4*>(x)[idx];
    a.x = fmaxf((a.x - g_mean[d4 + 0]) * g_scale[d4 + 0] + beta[d4 + 0], 0.f) + xv.x;
    a.y = fmaxf((a.y - g_mean[d4 + 1]) * g_scale[d4 + 1] + beta[d4 + 1], 0.f) + xv.y;
    a.z = fmaxf((a.z - g_mean[d4 + 2]) * g_scale[d4 + 2] + beta[d4 + 2], 0.f) + xv.z;
    a.w = fmaxf((a.w - g_mean[d4 + 3]) * g_scale[d4 + 3] + beta[d4 + 3], 0.f) + xv.w;
    reinterpret_cast<float4*>(out)[idx] = a;
}

extern "C" void kernel_launch(void* const* d_in, const int* in_sizes, int n_in,
                              void* d_out, int out_size) {
    const float* x     = (const float*)d_in[0];
    const void*  ei    = d_in[1];
    const float* W     = (const float*)d_in[2];
    const float* gamma = (const float*)d_in[4];
    const float* beta  = (const float*)d_in[5];
    int n = in_sizes[0] / D;
    int E = in_sizes[1] / 2;
    float* out = (float*)d_out;

    size_t nd = (size_t)n * D;
    if ((size_t)out_size > nd)
        cudaMemsetAsync(out + nd, 0, ((size_t)out_size - nd) * sizeof(float), 0);

    zero_kernel<<<(n + 255) / 256, 256>>>(n);
    detect_kernel<<<1, 32>>>((const unsigned int*)ei);
    convert_kernel<<<(E + 255) / 256, 256>>>(ei, E);   // fused degree

    int nb = (n + 1023) / 1024;
    scanA_kernel<<<nb, 256>>>(n);
    scanB_kernel<<<1, 32>>>(nb);
    scanC_kernel<<<(n + 255) / 256, 256>>>(n, E);      // fused dinv
    bucket_kernel<<<(E + 255) / 256, 256>>>(E);

    prep_w_kernel<<<64, 256>>>(W);
    cudaFuncSetAttribute(gemm_mma_kernel, cudaFuncAttributeMaxDynamicSharedMemorySize, GEMM_SMEM);
    gemm_mma_kernel<<<(n + 127) / 128, 256, GEMM_SMEM>>>(x, n);

    agg_kernel<<<((size_t)n * 32 + 255) / 256, 256>>>(out, n);
    reduce_kernel<<<512, 512>>>(out, n);
    stats_kernel<<<1, 128>>>(gamma, n);
    final_kernel<<<(n * 32 + 255) / 256, 256>>>(out, x, beta, n);
}